// round 1
// baseline (speedup 1.0000x reference)
#include <cuda_runtime.h>
#include <math.h>

#define H128 128
#define NFACT 100000
#define NCOMP 5000
#define NE 500000
#define NBATCH 64
#define DFACT 384
#define DCOMP 64

// ------------------------- static scratch (device .bss) -------------------------
__device__ float g_xf  [NFACT * H128];
__device__ float g_xf2 [NFACT * H128];
__device__ float g_aggf[NFACT * H128];
__device__ float g_xc  [NCOMP * H128];
__device__ float g_xc2 [NCOMP * H128];
__device__ float g_aggc[NCOMP * H128];
__device__ float g_wf2c[NE];
__device__ float g_wc2f[NE];
__device__ int   g_srcs_f2c[NE];
__device__ float g_ws_f2c  [NE];
__device__ int   g_srcs_c2f[NE];
__device__ float g_ws_c2f  [NE];
__device__ int   g_off_c[NCOMP + 1];
__device__ int   g_off_f[NFACT + 1];
__device__ int   g_cur_c[NCOMP];
__device__ int   g_cur_f[NFACT];
__device__ int   g_cnt_c[NCOMP];
__device__ int   g_cnt_f[NFACT];
__device__ int   g_bsums[256];
__device__ float g_pool [NBATCH * 256];
__device__ float g_pcnt [2 * NBATCH];
__device__ float g_pmean[NBATCH * 256];

// ------------------------- edge gate MLP -------------------------
__global__ void edge_gate_k(const float* __restrict__ ea,
                            const float* __restrict__ eW1, const float* __restrict__ eb1,
                            const float* __restrict__ eW2, const float* __restrict__ eb2,
                            const float* __restrict__ eW3, const float* __restrict__ eb3,
                            float* __restrict__ w)
{
    __shared__ float sW1[11 * 32], sb1[32], sW2[32 * 16], sb2[16], sW3[16], sb3;
    int tid = threadIdx.x;
    for (int i = tid; i < 11 * 32; i += blockDim.x) sW1[i] = eW1[i];
    for (int i = tid; i < 32 * 16; i += blockDim.x) sW2[i] = eW2[i];
    if (tid < 32) sb1[tid] = eb1[tid];
    if (tid < 16) { sb2[tid] = eb2[tid]; sW3[tid] = eW3[tid]; }
    if (tid == 0) sb3 = eb3[0];
    __syncthreads();

    int e = blockIdx.x * blockDim.x + tid;
    if (e >= NE) return;

    float sent  = fminf(fmaxf(ea[2 * e + 0], -1.f), 1.f);
    float decay = ea[2 * e + 1];
    float dt = fmaxf(-logf(fmaxf(decay, 1e-6f)) * 100.0f, 0.f);   // LAM = 0.01
    float ds = fminf(fmaxf(dt * (1.f / 30.f), 0.f), 12.f);

    float x[11];
    x[0] = sent;
    x[1] = log1pf(dt);
    x[2] = sinf(ds);       x[3] = sinf(2.f * ds);
    x[4] = sinf(3.f * ds); x[5] = sinf(4.f * ds);
    x[6] = cosf(ds);       x[7] = cosf(2.f * ds);
    x[8] = cosf(3.f * ds); x[9] = cosf(4.f * ds);
    x[10] = ds;

    float h1[32];
    #pragma unroll
    for (int j = 0; j < 32; j++) {
        float a = sb1[j];
        #pragma unroll
        for (int i = 0; i < 11; i++) a += x[i] * sW1[i * 32 + j];
        h1[j] = fmaxf(a, 0.f);
    }
    float h2[16];
    #pragma unroll
    for (int j = 0; j < 16; j++) {
        float a = sb2[j];
        #pragma unroll
        for (int i = 0; i < 32; i++) a += h1[i] * sW2[i * 16 + j];
        h2[j] = fmaxf(a, 0.f);
    }
    float z = sb3;
    #pragma unroll
    for (int i = 0; i < 16; i++) z += h2[i] * sW3[i];
    w[e] = 1.f / (1.f + expf(-z));
}

// ------------------------- CSR build: histogram / scan / scatter -------------------------
__global__ void hist_k(const int* __restrict__ dst, int* __restrict__ cnt, int n)
{
    int e = blockIdx.x * blockDim.x + threadIdx.x;
    if (e < n) atomicAdd(&cnt[dst[e]], 1);
}

__global__ void scan_block_k(const int* __restrict__ in, int* __restrict__ out,
                             int* __restrict__ bsums, int n)
{
    __shared__ int s[1024];
    int tid = threadIdx.x;
    int i = blockIdx.x * 1024 + tid;
    int v = (i < n) ? in[i] : 0;
    s[tid] = v;
    __syncthreads();
    for (int o = 1; o < 1024; o <<= 1) {
        int t = 0;
        if (tid >= o) t = s[tid - o];
        __syncthreads();
        if (tid >= o) s[tid] += t;
        __syncthreads();
    }
    if (i < n) out[i] = s[tid] - v;               // exclusive
    if (tid == 1023) bsums[blockIdx.x] = s[1023]; // block total
}

__global__ void scan_sums_k(int* __restrict__ bsums, int nb)
{
    __shared__ int s[128];
    int tid = threadIdx.x;
    int v = (tid < nb) ? bsums[tid] : 0;
    s[tid] = v;
    __syncthreads();
    for (int o = 1; o < 128; o <<= 1) {
        int t = 0;
        if (tid >= o) t = s[tid - o];
        __syncthreads();
        if (tid >= o) s[tid] += t;
        __syncthreads();
    }
    if (tid < nb) bsums[tid] = s[tid] - v;        // exclusive block prefix
}

__global__ void scan_add_k(int* __restrict__ off, int* __restrict__ cur,
                           const int* __restrict__ bsums, int n, int total)
{
    int i = blockIdx.x * 1024 + threadIdx.x;
    if (i < n) {
        int v = off[i] + bsums[blockIdx.x];
        off[i] = v;
        cur[i] = v;
    }
    if (i == 0) off[n] = total;
}

__global__ void scatter_k(const int* __restrict__ src, const int* __restrict__ dst,
                          const float* __restrict__ w, int* __restrict__ cur,
                          int* __restrict__ srcs_s, float* __restrict__ ws_s, int n)
{
    int e = blockIdx.x * blockDim.x + threadIdx.x;
    if (e >= n) return;
    int d = dst[e];
    int p = atomicAdd(&cur[d], 1);
    srcs_s[p] = src[e];
    ws_s[p]   = w[e];
}

// ------------------------- gather-side aggregation (no atomics) -------------------------
__global__ void aggregate_k(const int* __restrict__ off, const int* __restrict__ srcs,
                            const float* __restrict__ ws, const float* __restrict__ x,
                            float* __restrict__ out, int n)
{
    int node = blockIdx.x * 2 + (threadIdx.x >> 7);
    int c = threadIdx.x & 127;
    if (node >= n) return;
    int s = off[node], e = off[node + 1];
    float acc = 0.f;
    int i = s;
    for (; i + 4 <= e; i += 4) {
        int s0 = __ldg(&srcs[i]);     int s1 = __ldg(&srcs[i + 1]);
        int s2 = __ldg(&srcs[i + 2]); int s3 = __ldg(&srcs[i + 3]);
        float w0 = __ldg(&ws[i]);     float w1 = __ldg(&ws[i + 1]);
        float w2 = __ldg(&ws[i + 2]); float w3 = __ldg(&ws[i + 3]);
        float x0 = __ldg(&x[(size_t)s0 * 128 + c]);
        float x1 = __ldg(&x[(size_t)s1 * 128 + c]);
        float x2 = __ldg(&x[(size_t)s2 * 128 + c]);
        float x3 = __ldg(&x[(size_t)s3 * 128 + c]);
        acc += x0 * w0 + x1 * w1 + x2 * w2 + x3 * w3;
    }
    for (; i < e; i++)
        acc += __ldg(&x[(size_t)__ldg(&srcs[i]) * 128 + c]) * __ldg(&ws[i]);
    out[(size_t)node * 128 + c] = acc;
}

// ------------------------- SGEMM: C[M,128] = relu(A[M,K] @ B[K,128] + bias) -------------------------
__global__ void __launch_bounds__(128) gemm_in_k(
    const float* __restrict__ A, const float* __restrict__ B,
    const float* __restrict__ bias, float* __restrict__ C, int M, int K)
{
    __shared__ float As[16][64];
    __shared__ float Bs[16][128];
    int tid = threadIdx.x;
    int m0 = blockIdx.x * 64;
    int ty = tid >> 4;   // 0..7 : rows ty*8..+7
    int tx = tid & 15;   // 0..15: cols tx*8..+7
    float acc[8][8] = {};

    int nk = K >> 4;
    for (int t = 0; t < nk; t++) {
        int k0 = t << 4;
        #pragma unroll
        for (int i = 0; i < 2; i++) {
            int r  = (tid >> 2) + i * 32;
            int c4 = tid & 3;
            float4 v = make_float4(0.f, 0.f, 0.f, 0.f);
            if (m0 + r < M)
                v = *(const float4*)&A[(size_t)(m0 + r) * K + k0 + c4 * 4];
            As[c4 * 4 + 0][r] = v.x; As[c4 * 4 + 1][r] = v.y;
            As[c4 * 4 + 2][r] = v.z; As[c4 * 4 + 3][r] = v.w;
        }
        #pragma unroll
        for (int i = 0; i < 4; i++) {
            int r  = (tid >> 5) + i * 4;
            int c4 = tid & 31;
            *(float4*)&Bs[r][c4 * 4] = *(const float4*)&B[(size_t)(k0 + r) * 128 + c4 * 4];
        }
        __syncthreads();
        #pragma unroll
        for (int k = 0; k < 16; k++) {
            float a[8], b[8];
            *(float4*)&a[0] = *(float4*)&As[k][ty * 8];
            *(float4*)&a[4] = *(float4*)&As[k][ty * 8 + 4];
            *(float4*)&b[0] = *(float4*)&Bs[k][tx * 8];
            *(float4*)&b[4] = *(float4*)&Bs[k][tx * 8 + 4];
            #pragma unroll
            for (int i = 0; i < 8; i++)
                #pragma unroll
                for (int j = 0; j < 8; j++)
                    acc[i][j] += a[i] * b[j];
        }
        __syncthreads();
    }
    #pragma unroll
    for (int i = 0; i < 8; i++) {
        int r = m0 + ty * 8 + i;
        if (r < M) {
            #pragma unroll
            for (int j = 0; j < 8; j += 4) {
                float4 o;
                o.x = fmaxf(acc[i][j + 0] + bias[tx * 8 + j + 0], 0.f);
                o.y = fmaxf(acc[i][j + 1] + bias[tx * 8 + j + 1], 0.f);
                o.z = fmaxf(acc[i][j + 2] + bias[tx * 8 + j + 2], 0.f);
                o.w = fmaxf(acc[i][j + 3] + bias[tx * 8 + j + 3], 0.f);
                *(float4*)&C[(size_t)r * 128 + tx * 8 + j] = o;
            }
        }
    }
}

// C[M,128] = relu(A1@B1 + A2@B2 + bias) + prev    (A1,A2: Mx128; B1,B2: 128x128)
__global__ void __launch_bounds__(128) gemm_dual_k(
    const float* __restrict__ A1, const float* __restrict__ B1,
    const float* __restrict__ A2, const float* __restrict__ B2,
    const float* __restrict__ bias, const float* __restrict__ prev,
    float* __restrict__ C, int M)
{
    __shared__ float As[16][64];
    __shared__ float Bs[16][128];
    int tid = threadIdx.x;
    int m0 = blockIdx.x * 64;
    int ty = tid >> 4;
    int tx = tid & 15;
    float acc[8][8] = {};

    for (int t = 0; t < 16; t++) {
        const float* A = (t < 8) ? A1 : A2;
        const float* B = (t < 8) ? B1 : B2;
        int k0 = ((t < 8) ? t : (t - 8)) << 4;
        #pragma unroll
        for (int i = 0; i < 2; i++) {
            int r  = (tid >> 2) + i * 32;
            int c4 = tid & 3;
            float4 v = make_float4(0.f, 0.f, 0.f, 0.f);
            if (m0 + r < M)
                v = *(const float4*)&A[(size_t)(m0 + r) * 128 + k0 + c4 * 4];
            As[c4 * 4 + 0][r] = v.x; As[c4 * 4 + 1][r] = v.y;
            As[c4 * 4 + 2][r] = v.z; As[c4 * 4 + 3][r] = v.w;
        }
        #pragma unroll
        for (int i = 0; i < 4; i++) {
            int r  = (tid >> 5) + i * 4;
            int c4 = tid & 31;
            *(float4*)&Bs[r][c4 * 4] = *(const float4*)&B[(size_t)(k0 + r) * 128 + c4 * 4];
        }
        __syncthreads();
        #pragma unroll
        for (int k = 0; k < 16; k++) {
            float a[8], b[8];
            *(float4*)&a[0] = *(float4*)&As[k][ty * 8];
            *(float4*)&a[4] = *(float4*)&As[k][ty * 8 + 4];
            *(float4*)&b[0] = *(float4*)&Bs[k][tx * 8];
            *(float4*)&b[4] = *(float4*)&Bs[k][tx * 8 + 4];
            #pragma unroll
            for (int i = 0; i < 8; i++)
                #pragma unroll
                for (int j = 0; j < 8; j++)
                    acc[i][j] += a[i] * b[j];
        }
        __syncthreads();
    }
    #pragma unroll
    for (int i = 0; i < 8; i++) {
        int r = m0 + ty * 8 + i;
        if (r < M) {
            #pragma unroll
            for (int j = 0; j < 8; j += 4) {
                float4 p = *(const float4*)&prev[(size_t)r * 128 + tx * 8 + j];
                float4 o;
                o.x = fmaxf(acc[i][j + 0] + bias[tx * 8 + j + 0], 0.f) + p.x;
                o.y = fmaxf(acc[i][j + 1] + bias[tx * 8 + j + 1], 0.f) + p.y;
                o.z = fmaxf(acc[i][j + 2] + bias[tx * 8 + j + 2], 0.f) + p.z;
                o.w = fmaxf(acc[i][j + 3] + bias[tx * 8 + j + 3], 0.f) + p.w;
                *(float4*)&C[(size_t)r * 128 + tx * 8 + j] = o;
            }
        }
    }
}

// ------------------------- layernorm (in place, one row per block) -------------------------
__global__ void layernorm_k(float* __restrict__ x, const float* __restrict__ scale,
                            const float* __restrict__ bias, int n)
{
    int row = blockIdx.x;
    if (row >= n) return;
    int c = threadIdx.x;
    float v = x[(size_t)row * 128 + c];
    float s = v, s2 = v * v;
    #pragma unroll
    for (int o = 16; o > 0; o >>= 1) {
        s  += __shfl_xor_sync(0xffffffffu, s, o);
        s2 += __shfl_xor_sync(0xffffffffu, s2, o);
    }
    __shared__ float rs[4], rs2[4];
    if ((c & 31) == 0) { rs[c >> 5] = s; rs2[c >> 5] = s2; }
    __syncthreads();
    s  = rs[0] + rs[1] + rs[2] + rs[3];
    s2 = rs2[0] + rs2[1] + rs2[2] + rs2[3];
    float mu  = s * (1.f / 128.f);
    float var = s2 * (1.f / 128.f) - mu * mu;
    x[(size_t)row * 128 + c] = (v - mu) * rsqrtf(var + 1e-5f) * scale[c] + bias[c];
}

// ------------------------- pooling + classifier -------------------------
__global__ void pool_k(const float* __restrict__ x, const int* __restrict__ batch,
                       float* __restrict__ pool, float* __restrict__ pcnt,
                       int n, int coloff, int cntoff)
{
    int idx = blockIdx.x * blockDim.x + threadIdx.x;
    if (idx >= n * 128) return;
    int r = idx >> 7, c = idx & 127;
    int b = batch[r];
    atomicAdd(&pool[b * 256 + coloff + c], x[idx]);
    if (c == 0) atomicAdd(&pcnt[cntoff + b], 1.f);
}

__global__ void pmean_k(const float* __restrict__ pool, const float* __restrict__ pcnt,
                        float* __restrict__ pmean)
{
    int i = blockIdx.x * blockDim.x + threadIdx.x;
    if (i >= NBATCH * 256) return;
    int b = i >> 8, k = i & 255;
    float cnt = pcnt[(k < 128 ? 0 : NBATCH) + b];
    pmean[i] = pool[i] / fmaxf(cnt, 1.f);
}

__global__ void classifier_k(const float* __restrict__ pmean,
                             const float* __restrict__ Wc1, const float* __restrict__ bc1,
                             const float* __restrict__ Wc2, const float* __restrict__ bc2,
                             float* __restrict__ out)
{
    __shared__ float h[64][129];
    int c = threadIdx.x;  // 128 threads
    for (int b = 0; b < 64; b++) {
        float a = bc1[c];
        #pragma unroll 4
        for (int k = 0; k < 256; k++) a += pmean[b * 256 + k] * Wc1[k * 128 + c];
        h[b][c] = fmaxf(a, 0.f);
    }
    __syncthreads();
    if (c < 64) {
        float a = bc2[0];
        #pragma unroll 4
        for (int k = 0; k < 128; k++) a += h[c][k] * Wc2[k];
        out[c] = a;
    }
}

// ------------------------- host orchestration -------------------------
extern "C" void kernel_launch(void* const* d_in, const int* in_sizes, int n_in,
                              void* d_out, int out_size)
{
    const float* x_fact     = (const float*)d_in[0];
    const float* x_comp     = (const float*)d_in[1];
    const float* ea_f2c     = (const float*)d_in[2];
    const float* ea_c2f     = (const float*)d_in[3];
    const int*   ei_f2c_src = (const int*)d_in[4];
    const int*   ei_f2c_dst = (const int*)d_in[5];
    const int*   ei_c2f_src = (const int*)d_in[6];
    const int*   ei_c2f_dst = (const int*)d_in[7];
    const int*   fact_batch = (const int*)d_in[8];
    const int*   comp_batch = (const int*)d_in[9];
    const float* W_in_fact  = (const float*)d_in[10];
    const float* b_in_fact  = (const float*)d_in[11];
    const float* W_in_comp  = (const float*)d_in[12];
    const float* b_in_comp  = (const float*)d_in[13];
    const float* eW1 = (const float*)d_in[14];
    const float* eb1 = (const float*)d_in[15];
    const float* eW2 = (const float*)d_in[16];
    const float* eb2 = (const float*)d_in[17];
    const float* eW3 = (const float*)d_in[18];
    const float* eb3 = (const float*)d_in[19];
    const float* W_rel    = (const float*)d_in[20];
    const float* b_rel    = (const float*)d_in[21];
    const float* W_root   = (const float*)d_in[22];
    const float* ln_scale = (const float*)d_in[23];
    const float* ln_bias  = (const float*)d_in[24];
    const float* Wc1 = (const float*)d_in[25];
    const float* bc1 = (const float*)d_in[26];
    const float* Wc2 = (const float*)d_in[27];
    const float* bc2 = (const float*)d_in[28];
    float* out = (float*)d_out;

    float *xf, *xf2, *aggf, *xc, *xc2, *aggc, *wf2c, *wc2f;
    float *ws_f2c, *ws_c2f, *pool, *pcnt, *pmean;
    int *srcs_f2c, *srcs_c2f, *off_c, *off_f, *cur_c, *cur_f, *cnt_c, *cnt_f, *bsums;
    cudaGetSymbolAddress((void**)&xf,   g_xf);
    cudaGetSymbolAddress((void**)&xf2,  g_xf2);
    cudaGetSymbolAddress((void**)&aggf, g_aggf);
    cudaGetSymbolAddress((void**)&xc,   g_xc);
    cudaGetSymbolAddress((void**)&xc2,  g_xc2);
    cudaGetSymbolAddress((void**)&aggc, g_aggc);
    cudaGetSymbolAddress((void**)&wf2c, g_wf2c);
    cudaGetSymbolAddress((void**)&wc2f, g_wc2f);
    cudaGetSymbolAddress((void**)&srcs_f2c, g_srcs_f2c);
    cudaGetSymbolAddress((void**)&ws_f2c,   g_ws_f2c);
    cudaGetSymbolAddress((void**)&srcs_c2f, g_srcs_c2f);
    cudaGetSymbolAddress((void**)&ws_c2f,   g_ws_c2f);
    cudaGetSymbolAddress((void**)&off_c, g_off_c);
    cudaGetSymbolAddress((void**)&off_f, g_off_f);
    cudaGetSymbolAddress((void**)&cur_c, g_cur_c);
    cudaGetSymbolAddress((void**)&cur_f, g_cur_f);
    cudaGetSymbolAddress((void**)&cnt_c, g_cnt_c);
    cudaGetSymbolAddress((void**)&cnt_f, g_cnt_f);
    cudaGetSymbolAddress((void**)&bsums, g_bsums);
    cudaGetSymbolAddress((void**)&pool,  g_pool);
    cudaGetSymbolAddress((void**)&pcnt,  g_pcnt);
    cudaGetSymbolAddress((void**)&pmean, g_pmean);

    cudaMemsetAsync(cnt_c, 0, NCOMP * sizeof(int));
    cudaMemsetAsync(cnt_f, 0, NFACT * sizeof(int));
    cudaMemsetAsync(pool,  0, NBATCH * 256 * sizeof(float));
    cudaMemsetAsync(pcnt,  0, 2 * NBATCH * sizeof(float));

    const int EB = (NE + 255) / 256;

    // edge gates
    edge_gate_k<<<EB, 256>>>(ea_f2c, eW1, eb1, eW2, eb2, eW3, eb3, wf2c);
    edge_gate_k<<<EB, 256>>>(ea_c2f, eW1, eb1, eW2, eb2, eW3, eb3, wc2f);

    // CSR build: f2c (dst = comp)
    hist_k<<<EB, 256>>>(ei_f2c_dst, cnt_c, NE);
    int nbc = (NCOMP + 1023) / 1024;
    scan_block_k<<<nbc, 1024>>>(cnt_c, off_c, bsums, NCOMP);
    scan_sums_k<<<1, 128>>>(bsums, nbc);
    scan_add_k<<<nbc, 1024>>>(off_c, cur_c, bsums, NCOMP, NE);
    scatter_k<<<EB, 256>>>(ei_f2c_src, ei_f2c_dst, wf2c, cur_c, srcs_f2c, ws_f2c, NE);

    // CSR build: c2f (dst = fact)
    hist_k<<<EB, 256>>>(ei_c2f_dst, cnt_f, NE);
    int nbf = (NFACT + 1023) / 1024;
    scan_block_k<<<nbf, 1024>>>(cnt_f, off_f, bsums, NFACT);
    scan_sums_k<<<1, 128>>>(bsums, nbf);
    scan_add_k<<<nbf, 1024>>>(off_f, cur_f, bsums, NFACT, NE);
    scatter_k<<<EB, 256>>>(ei_c2f_src, ei_c2f_dst, wc2f, cur_f, srcs_c2f, ws_c2f, NE);

    // input MLPs
    gemm_in_k<<<(NFACT + 63) / 64, 128>>>(x_fact, W_in_fact, b_in_fact, xf, NFACT, DFACT);
    gemm_in_k<<<(NCOMP + 63) / 64, 128>>>(x_comp, W_in_comp, b_in_comp, xc, NCOMP, DCOMP);

    // message-passing layers
    float* cf = xf;  float* cc = xc;
    float* nf = xf2; float* nc = xc2;
    for (int l = 0; l < 2; l++) {
        aggregate_k<<<(NCOMP + 1) / 2, 256>>>(off_c, srcs_f2c, ws_f2c, cf, aggc, NCOMP);
        gemm_dual_k<<<(NCOMP + 63) / 64, 128>>>(aggc, W_rel + (l * 2 + 0) * 16384,
                                                cc,   W_root + (l * 2 + 0) * 16384,
                                                b_rel + (l * 2 + 0) * 128, cc, nc, NCOMP);
        aggregate_k<<<(NFACT + 1) / 2, 256>>>(off_f, srcs_c2f, ws_c2f, cc, aggf, NFACT);
        gemm_dual_k<<<(NFACT + 63) / 64, 128>>>(aggf, W_rel + (l * 2 + 1) * 16384,
                                                cf,   W_root + (l * 2 + 1) * 16384,
                                                b_rel + (l * 2 + 1) * 128, cf, nf, NFACT);
        layernorm_k<<<NFACT, 128>>>(nf, ln_scale,       ln_bias,       NFACT);
        layernorm_k<<<NCOMP, 128>>>(nc, ln_scale + 128, ln_bias + 128, NCOMP);
        float* t;
        t = cf; cf = nf; nf = t;
        t = cc; cc = nc; nc = t;
    }

    // pooling + classifier
    pool_k<<<(NFACT * 128 + 255) / 256, 256>>>(cf, fact_batch, pool, pcnt, NFACT, 0, 0);
    pool_k<<<(NCOMP * 128 + 255) / 256, 256>>>(cc, comp_batch, pool, pcnt, NCOMP, 128, NBATCH);
    pmean_k<<<64, 256>>>(pool, pcnt, pmean);
    classifier_k<<<1, 128>>>(pmean, Wc1, bc1, Wc2, bc2, out);
}

// round 4
// speedup vs baseline: 1.2221x; 1.2221x over previous
#include <cuda_runtime.h>
#include <math.h>
#include <stdint.h>

#define H128 128
#define NFACT 100000
#define NCOMP 5000
#define NE 500000
#define NBATCH 64
#define DFACT 384
#define DCOMP 64

// ------------------------- static scratch (device .bss) -------------------------
__device__ float g_xf  [NFACT * H128];
__device__ float g_xf2 [NFACT * H128];
__device__ float g_aggf[NFACT * H128];
__device__ float g_xc  [NCOMP * H128];
__device__ float g_xc2 [NCOMP * H128];
__device__ float g_aggc[NCOMP * H128];
__device__ float g_wf2c[NE];
__device__ float g_wc2f[NE];
__device__ int   g_srcs_f2c[NE];
__device__ float g_ws_f2c  [NE];
__device__ int   g_srcs_c2f[NE];
__device__ float g_ws_c2f  [NE];
__device__ int   g_off_c[NCOMP + 1];
__device__ int   g_off_f[NFACT + 1];
__device__ int   g_cur_c[NCOMP];
__device__ int   g_cur_f[NFACT];
__device__ int   g_cnt_c[NCOMP];
__device__ int   g_cnt_f[NFACT];
__device__ int   g_bsums[256];
__device__ float g_pool [NBATCH * 256];
__device__ float g_pcnt [2 * NBATCH];
__device__ float g_pmean[NBATCH * 256];
// transposed weights: Wt_in_fact [128x384], Wt_in_comp [128x64], Wt_rel[4][128x128], Wt_root[4][128x128]
#define WT_INF_OFF  0
#define WT_INC_OFF  (128 * 384)
#define WT_REL_OFF  (WT_INC_OFF + 128 * 64)
#define WT_ROOT_OFF (WT_REL_OFF + 4 * 128 * 128)
__device__ float g_wt[WT_ROOT_OFF + 4 * 128 * 128];

// ------------------------- tf32 mma.sync GEMM -------------------------
__device__ __forceinline__ uint32_t f2tf32(float f) {
    uint32_t u;
    asm("cvt.rna.tf32.f32 %0, %1;" : "=r"(u) : "f"(f));
    return u;
}
__device__ __forceinline__ void mma16n8k8(float* c, const uint32_t* a, const uint32_t* b) {
    asm volatile(
        "mma.sync.aligned.m16n8k8.row.col.f32.tf32.tf32.f32 "
        "{%0,%1,%2,%3}, {%4,%5,%6,%7}, {%8,%9}, {%0,%1,%2,%3};"
        : "+f"(c[0]), "+f"(c[1]), "+f"(c[2]), "+f"(c[3])
        : "r"(a[0]), "r"(a[1]), "r"(a[2]), "r"(a[3]), "r"(b[0]), "r"(b[1]));
}

// C[M,128] = relu( A1[M,K1] @ B1t^T + (A2[M,K2] @ B2t^T) + bias ) (+ prev)
// B1t/B2t pre-transposed: Bt[n][k] = W[k][n], row stride = K.
__global__ void __launch_bounds__(256) gemm_mma_k(
    const float* __restrict__ A1, const float* __restrict__ B1t, int K1,
    const float* __restrict__ A2, const float* __restrict__ B2t, int K2,
    const float* __restrict__ bias, const float* __restrict__ prev,
    float* __restrict__ C, int M)
{
    __shared__ uint32_t As[128][36];
    __shared__ uint32_t Bs[128][36];
    const int tid  = threadIdx.x;
    const int lane = tid & 31;
    const int warp = tid >> 5;
    const int wm   = warp & 3;     // M quadrant (rows wm*32..+31)
    const int wn   = warp >> 2;    // N half    (cols wn*64..+63)
    const int g    = lane >> 2;    // group id 0..7
    const int tg   = lane & 3;     // thread-in-group 0..3
    const int m0   = blockIdx.x * 128;

    float acc[2][8][4];
    #pragma unroll
    for (int mf = 0; mf < 2; mf++)
        #pragma unroll
        for (int nf = 0; nf < 8; nf++)
            #pragma unroll
            for (int i = 0; i < 4; i++) acc[mf][nf][i] = 0.f;

    const int nch1 = K1 >> 5;
    const int nch2 = K2 >> 5;
    const int total = nch1 + nch2;

    for (int ch = 0; ch < total; ch++) {
        const float* A; const float* B; int K, k0;
        if (ch < nch1) { A = A1; B = B1t; K = K1; k0 = ch << 5; }
        else           { A = A2; B = B2t; K = K2; k0 = (ch - nch1) << 5; }

        // A tile: 128 rows x 32 cols = 1024 float4, 4 per thread
        #pragma unroll
        for (int i = 0; i < 4; i++) {
            int idx = i * 256 + tid;
            int r = idx >> 3, c4 = idx & 7;
            float4 v = make_float4(0.f, 0.f, 0.f, 0.f);
            if (m0 + r < M) v = *(const float4*)&A[(size_t)(m0 + r) * K + k0 + c4 * 4];
            As[r][c4 * 4 + 0] = f2tf32(v.x);
            As[r][c4 * 4 + 1] = f2tf32(v.y);
            As[r][c4 * 4 + 2] = f2tf32(v.z);
            As[r][c4 * 4 + 3] = f2tf32(v.w);
        }
        // B tile: 128 N-rows x 32 cols
        #pragma unroll
        for (int i = 0; i < 4; i++) {
            int idx = i * 256 + tid;
            int r = idx >> 3, c4 = idx & 7;
            float4 v = *(const float4*)&B[(size_t)r * K + k0 + c4 * 4];
            Bs[r][c4 * 4 + 0] = f2tf32(v.x);
            Bs[r][c4 * 4 + 1] = f2tf32(v.y);
            Bs[r][c4 * 4 + 2] = f2tf32(v.z);
            Bs[r][c4 * 4 + 3] = f2tf32(v.w);
        }
        __syncthreads();

        #pragma unroll
        for (int s = 0; s < 4; s++) {
            const int kk = s * 8;
            uint32_t a[2][4], b[8][2];
            #pragma unroll
            for (int mf = 0; mf < 2; mf++) {
                int rb = wm * 32 + mf * 16;
                a[mf][0] = As[rb + g    ][kk + tg    ];
                a[mf][1] = As[rb + 8 + g][kk + tg    ];
                a[mf][2] = As[rb + g    ][kk + tg + 4];
                a[mf][3] = As[rb + 8 + g][kk + tg + 4];
            }
            #pragma unroll
            for (int nf = 0; nf < 8; nf++) {
                int cb = wn * 64 + nf * 8;
                b[nf][0] = Bs[cb + g][kk + tg    ];
                b[nf][1] = Bs[cb + g][kk + tg + 4];
            }
            #pragma unroll
            for (int mf = 0; mf < 2; mf++)
                #pragma unroll
                for (int nf = 0; nf < 8; nf++)
                    mma16n8k8(acc[mf][nf], a[mf], b[nf]);
        }
        __syncthreads();
    }

    // epilogue: bias + relu (+ prev residual)
    #pragma unroll
    for (int mf = 0; mf < 2; mf++) {
        #pragma unroll
        for (int nf = 0; nf < 8; nf++) {
            int col  = wn * 64 + nf * 8 + tg * 2;
            int row0 = m0 + wm * 32 + mf * 16 + g;
            float b0 = __ldg(&bias[col]);
            float b1 = __ldg(&bias[col + 1]);
            if (row0 < M) {
                float2 o;
                o.x = fmaxf(acc[mf][nf][0] + b0, 0.f);
                o.y = fmaxf(acc[mf][nf][1] + b1, 0.f);
                if (prev) {
                    float2 p = *(const float2*)&prev[(size_t)row0 * 128 + col];
                    o.x += p.x; o.y += p.y;
                }
                *(float2*)&C[(size_t)row0 * 128 + col] = o;
            }
            int row1 = row0 + 8;
            if (row1 < M) {
                float2 o;
                o.x = fmaxf(acc[mf][nf][2] + b0, 0.f);
                o.y = fmaxf(acc[mf][nf][3] + b1, 0.f);
                if (prev) {
                    float2 p = *(const float2*)&prev[(size_t)row1 * 128 + col];
                    o.x += p.x; o.y += p.y;
                }
                *(float2*)&C[(size_t)row1 * 128 + col] = o;
            }
        }
    }
}

// ------------------------- weight transpose (all mats in one launch) -------------------------
// GRID MUST COVER 4*128*128 = 65536 threads (bug in R2/R3: only 49152).
__global__ void transpose_all_k(const float* __restrict__ W_in_fact,
                                const float* __restrict__ W_in_comp,
                                const float* __restrict__ W_rel,
                                const float* __restrict__ W_root,
                                float* __restrict__ wt)
{
    int i = blockIdx.x * 256 + threadIdx.x;
    int total0 = 384 * 128;
    int total1 = 64 * 128;
    int total2 = 4 * 128 * 128;
    if (i < total0) {
        int k = i >> 7, n = i & 127;
        wt[WT_INF_OFF + n * 384 + k] = W_in_fact[i];
    }
    if (i < total1) {
        int k = i >> 7, n = i & 127;
        wt[WT_INC_OFF + n * 64 + k] = W_in_comp[i];
    }
    if (i < total2) {
        int m = i / 16384, r = i % 16384;
        int k = r >> 7, n = r & 127;
        wt[WT_REL_OFF  + m * 16384 + n * 128 + k] = W_rel[i];
        wt[WT_ROOT_OFF + m * 16384 + n * 128 + k] = W_root[i];
    }
}

// ------------------------- edge gate MLP -------------------------
__global__ void edge_gate_k(const float* __restrict__ ea,
                            const float* __restrict__ eW1, const float* __restrict__ eb1,
                            const float* __restrict__ eW2, const float* __restrict__ eb2,
                            const float* __restrict__ eW3, const float* __restrict__ eb3,
                            float* __restrict__ w)
{
    __shared__ float sW1[11 * 32], sb1[32], sW2[32 * 16], sb2[16], sW3[16], sb3;
    int tid = threadIdx.x;
    for (int i = tid; i < 11 * 32; i += blockDim.x) sW1[i] = eW1[i];
    for (int i = tid; i < 32 * 16; i += blockDim.x) sW2[i] = eW2[i];
    if (tid < 32) sb1[tid] = eb1[tid];
    if (tid < 16) { sb2[tid] = eb2[tid]; sW3[tid] = eW3[tid]; }
    if (tid == 0) sb3 = eb3[0];
    __syncthreads();

    int e = blockIdx.x * blockDim.x + tid;
    if (e >= NE) return;

    float sent  = fminf(fmaxf(ea[2 * e + 0], -1.f), 1.f);
    float decay = ea[2 * e + 1];
    float dt = fmaxf(-logf(fmaxf(decay, 1e-6f)) * 100.0f, 0.f);   // LAM = 0.01
    float ds = fminf(fmaxf(dt * (1.f / 30.f), 0.f), 12.f);

    float x[11];
    x[0] = sent;
    x[1] = log1pf(dt);
    x[2] = sinf(ds);       x[3] = sinf(2.f * ds);
    x[4] = sinf(3.f * ds); x[5] = sinf(4.f * ds);
    x[6] = cosf(ds);       x[7] = cosf(2.f * ds);
    x[8] = cosf(3.f * ds); x[9] = cosf(4.f * ds);
    x[10] = ds;

    float h1[32];
    #pragma unroll
    for (int j = 0; j < 32; j++) {
        float a = sb1[j];
        #pragma unroll
        for (int i = 0; i < 11; i++) a += x[i] * sW1[i * 32 + j];
        h1[j] = fmaxf(a, 0.f);
    }
    float h2[16];
    #pragma unroll
    for (int j = 0; j < 16; j++) {
        float a = sb2[j];
        #pragma unroll
        for (int i = 0; i < 32; i++) a += h1[i] * sW2[i * 16 + j];
        h2[j] = fmaxf(a, 0.f);
    }
    float z = sb3;
    #pragma unroll
    for (int i = 0; i < 16; i++) z += h2[i] * sW3[i];
    w[e] = 1.f / (1.f + expf(-z));
}

// ------------------------- CSR build -------------------------
__global__ void hist_k(const int* __restrict__ dst, int* __restrict__ cnt, int n)
{
    int e = blockIdx.x * blockDim.x + threadIdx.x;
    if (e < n) atomicAdd(&cnt[dst[e]], 1);
}

__global__ void scan_block_k(const int* __restrict__ in, int* __restrict__ out,
                             int* __restrict__ bsums, int n)
{
    __shared__ int s[1024];
    int tid = threadIdx.x;
    int i = blockIdx.x * 1024 + tid;
    int v = (i < n) ? in[i] : 0;
    s[tid] = v;
    __syncthreads();
    for (int o = 1; o < 1024; o <<= 1) {
        int t = 0;
        if (tid >= o) t = s[tid - o];
        __syncthreads();
        if (tid >= o) s[tid] += t;
        __syncthreads();
    }
    if (i < n) out[i] = s[tid] - v;
    if (tid == 1023) bsums[blockIdx.x] = s[1023];
}

__global__ void scan_sums_k(int* __restrict__ bsums, int nb)
{
    __shared__ int s[128];
    int tid = threadIdx.x;
    int v = (tid < nb) ? bsums[tid] : 0;
    s[tid] = v;
    __syncthreads();
    for (int o = 1; o < 128; o <<= 1) {
        int t = 0;
        if (tid >= o) t = s[tid - o];
        __syncthreads();
        if (tid >= o) s[tid] += t;
        __syncthreads();
    }
    if (tid < nb) bsums[tid] = s[tid] - v;
}

__global__ void scan_add_k(int* __restrict__ off, int* __restrict__ cur,
                           const int* __restrict__ bsums, int n, int total)
{
    int i = blockIdx.x * 1024 + threadIdx.x;
    if (i < n) {
        int v = off[i] + bsums[blockIdx.x];
        off[i] = v;
        cur[i] = v;
    }
    if (i == 0) off[n] = total;
}

__global__ void scatter_k(const int* __restrict__ src, const int* __restrict__ dst,
                          const float* __restrict__ w, int* __restrict__ cur,
                          int* __restrict__ srcs_s, float* __restrict__ ws_s, int n)
{
    int e = blockIdx.x * blockDim.x + threadIdx.x;
    if (e >= n) return;
    int d = dst[e];
    int p = atomicAdd(&cur[d], 1);
    srcs_s[p] = src[e];
    ws_s[p]   = w[e];
}

// ------------------------- gather-side aggregation (no atomics) -------------------------
__global__ void aggregate_k(const int* __restrict__ off, const int* __restrict__ srcs,
                            const float* __restrict__ ws, const float* __restrict__ x,
                            float* __restrict__ out, int n)
{
    int node = blockIdx.x * 2 + (threadIdx.x >> 7);
    int c = threadIdx.x & 127;
    if (node >= n) return;
    int s = off[node], e = off[node + 1];
    float acc = 0.f;
    int i = s;
    for (; i + 4 <= e; i += 4) {
        int s0 = __ldg(&srcs[i]);     int s1 = __ldg(&srcs[i + 1]);
        int s2 = __ldg(&srcs[i + 2]); int s3 = __ldg(&srcs[i + 3]);
        float w0 = __ldg(&ws[i]);     float w1 = __ldg(&ws[i + 1]);
        float w2 = __ldg(&ws[i + 2]); float w3 = __ldg(&ws[i + 3]);
        float x0 = __ldg(&x[(size_t)s0 * 128 + c]);
        float x1 = __ldg(&x[(size_t)s1 * 128 + c]);
        float x2 = __ldg(&x[(size_t)s2 * 128 + c]);
        float x3 = __ldg(&x[(size_t)s3 * 128 + c]);
        acc += x0 * w0 + x1 * w1 + x2 * w2 + x3 * w3;
    }
    for (; i < e; i++)
        acc += __ldg(&x[(size_t)__ldg(&srcs[i]) * 128 + c]) * __ldg(&ws[i]);
    out[(size_t)node * 128 + c] = acc;
}

// ------------------------- layernorm (in place, one row per block) -------------------------
__global__ void layernorm_k(float* __restrict__ x, const float* __restrict__ scale,
                            const float* __restrict__ bias, int n)
{
    int row = blockIdx.x;
    if (row >= n) return;
    int c = threadIdx.x;
    float v = x[(size_t)row * 128 + c];
    float s = v, s2 = v * v;
    #pragma unroll
    for (int o = 16; o > 0; o >>= 1) {
        s  += __shfl_xor_sync(0xffffffffu, s, o);
        s2 += __shfl_xor_sync(0xffffffffu, s2, o);
    }
    __shared__ float rs[4], rs2[4];
    if ((c & 31) == 0) { rs[c >> 5] = s; rs2[c >> 5] = s2; }
    __syncthreads();
    s  = rs[0] + rs[1] + rs[2] + rs[3];
    s2 = rs2[0] + rs2[1] + rs2[2] + rs2[3];
    float mu  = s * (1.f / 128.f);
    float var = s2 * (1.f / 128.f) - mu * mu;
    x[(size_t)row * 128 + c] = (v - mu) * rsqrtf(var + 1e-5f) * scale[c] + bias[c];
}

// ------------------------- pooling + classifier -------------------------
__global__ void pool_k(const float* __restrict__ x, const int* __restrict__ batch,
                       float* __restrict__ pool, float* __restrict__ pcnt,
                       int n, int coloff, int cntoff)
{
    int idx = blockIdx.x * blockDim.x + threadIdx.x;
    if (idx >= n * 128) return;
    int r = idx >> 7, c = idx & 127;
    int b = batch[r];
    atomicAdd(&pool[b * 256 + coloff + c], x[idx]);
    if (c == 0) atomicAdd(&pcnt[cntoff + b], 1.f);
}

__global__ void pmean_k(const float* __restrict__ pool, const float* __restrict__ pcnt,
                        float* __restrict__ pmean)
{
    int i = blockIdx.x * blockDim.x + threadIdx.x;
    if (i >= NBATCH * 256) return;
    int b = i >> 8, k = i & 255;
    float cnt = pcnt[(k < 128 ? 0 : NBATCH) + b];
    pmean[i] = pool[i] / fmaxf(cnt, 1.f);
}

__global__ void classifier_k(const float* __restrict__ pmean,
                             const float* __restrict__ Wc1, const float* __restrict__ bc1,
                             const float* __restrict__ Wc2, const float* __restrict__ bc2,
                             float* __restrict__ out)
{
    __shared__ float h[64][129];
    int c = threadIdx.x;  // 128 threads
    for (int b = 0; b < 64; b++) {
        float a = bc1[c];
        #pragma unroll 4
        for (int k = 0; k < 256; k++) a += pmean[b * 256 + k] * Wc1[k * 128 + c];
        h[b][c] = fmaxf(a, 0.f);
    }
    __syncthreads();
    if (c < 64) {
        float a = bc2[0];
        #pragma unroll 4
        for (int k = 0; k < 128; k++) a += h[c][k] * Wc2[k];
        out[c] = a;
    }
}

// ------------------------- host orchestration -------------------------
extern "C" void kernel_launch(void* const* d_in, const int* in_sizes, int n_in,
                              void* d_out, int out_size)
{
    const float* x_fact     = (const float*)d_in[0];
    const float* x_comp     = (const float*)d_in[1];
    const float* ea_f2c     = (const float*)d_in[2];
    const float* ea_c2f     = (const float*)d_in[3];
    const int*   ei_f2c_src = (const int*)d_in[4];
    const int*   ei_f2c_dst = (const int*)d_in[5];
    const int*   ei_c2f_src = (const int*)d_in[6];
    const int*   ei_c2f_dst = (const int*)d_in[7];
    const int*   fact_batch = (const int*)d_in[8];
    const int*   comp_batch = (const int*)d_in[9];
    const float* W_in_fact  = (const float*)d_in[10];
    const float* b_in_fact  = (const float*)d_in[11];
    const float* W_in_comp  = (const float*)d_in[12];
    const float* b_in_comp  = (const float*)d_in[13];
    const float* eW1 = (const float*)d_in[14];
    const float* eb1 = (const float*)d_in[15];
    const float* eW2 = (const float*)d_in[16];
    const float* eb2 = (const float*)d_in[17];
    const float* eW3 = (const float*)d_in[18];
    const float* eb3 = (const float*)d_in[19];
    const float* W_rel    = (const float*)d_in[20];
    const float* b_rel    = (const float*)d_in[21];
    const float* W_root   = (const float*)d_in[22];
    const float* ln_scale = (const float*)d_in[23];
    const float* ln_bias  = (const float*)d_in[24];
    const float* Wc1 = (const float*)d_in[25];
    const float* bc1 = (const float*)d_in[26];
    const float* Wc2 = (const float*)d_in[27];
    const float* bc2 = (const float*)d_in[28];
    float* out = (float*)d_out;

    float *xf, *xf2, *aggf, *xc, *xc2, *aggc, *wf2c, *wc2f;
    float *ws_f2c, *ws_c2f, *pool, *pcnt, *pmean, *wt;
    int *srcs_f2c, *srcs_c2f, *off_c, *off_f, *cur_c, *cur_f, *cnt_c, *cnt_f, *bsums;
    cudaGetSymbolAddress((void**)&xf,   g_xf);
    cudaGetSymbolAddress((void**)&xf2,  g_xf2);
    cudaGetSymbolAddress((void**)&aggf, g_aggf);
    cudaGetSymbolAddress((void**)&xc,   g_xc);
    cudaGetSymbolAddress((void**)&xc2,  g_xc2);
    cudaGetSymbolAddress((void**)&aggc, g_aggc);
    cudaGetSymbolAddress((void**)&wf2c, g_wf2c);
    cudaGetSymbolAddress((void**)&wc2f, g_wc2f);
    cudaGetSymbolAddress((void**)&srcs_f2c, g_srcs_f2c);
    cudaGetSymbolAddress((void**)&ws_f2c,   g_ws_f2c);
    cudaGetSymbolAddress((void**)&srcs_c2f, g_srcs_c2f);
    cudaGetSymbolAddress((void**)&ws_c2f,   g_ws_c2f);
    cudaGetSymbolAddress((void**)&off_c, g_off_c);
    cudaGetSymbolAddress((void**)&off_f, g_off_f);
    cudaGetSymbolAddress((void**)&cur_c, g_cur_c);
    cudaGetSymbolAddress((void**)&cur_f, g_cur_f);
    cudaGetSymbolAddress((void**)&cnt_c, g_cnt_c);
    cudaGetSymbolAddress((void**)&cnt_f, g_cnt_f);
    cudaGetSymbolAddress((void**)&bsums, g_bsums);
    cudaGetSymbolAddress((void**)&pool,  g_pool);
    cudaGetSymbolAddress((void**)&pcnt,  g_pcnt);
    cudaGetSymbolAddress((void**)&pmean, g_pmean);
    cudaGetSymbolAddress((void**)&wt,    g_wt);

    cudaMemsetAsync(cnt_c, 0, NCOMP * sizeof(int));
    cudaMemsetAsync(cnt_f, 0, NFACT * sizeof(int));
    cudaMemsetAsync(pool,  0, NBATCH * 256 * sizeof(float));
    cudaMemsetAsync(pcnt,  0, 2 * NBATCH * sizeof(float));

    const int EB = (NE + 255) / 256;
    const int GF = (NFACT + 127) / 128;  // 782 tiles
    const int GC = (NCOMP + 127) / 128;  // 40 tiles

    // weight transposes first (cover 4*128*128 = 65536 indices -> 256 blocks)
    transpose_all_k<<<256, 256>>>(W_in_fact, W_in_comp, W_rel, W_root, wt);

    // edge gates + CSR histograms (independent of GEMMs)
    edge_gate_k<<<EB, 256>>>(ea_f2c, eW1, eb1, eW2, eb2, eW3, eb3, wf2c);
    edge_gate_k<<<EB, 256>>>(ea_c2f, eW1, eb1, eW2, eb2, eW3, eb3, wc2f);
    hist_k<<<EB, 256>>>(ei_f2c_dst, cnt_c, NE);
    hist_k<<<EB, 256>>>(ei_c2f_dst, cnt_f, NE);

    // input MLPs (tf32 mma)
    gemm_mma_k<<<GF, 256>>>(x_fact, wt + WT_INF_OFF, DFACT,
                            nullptr, nullptr, 0,
                            b_in_fact, nullptr, xf, NFACT);
    gemm_mma_k<<<GC, 256>>>(x_comp, wt + WT_INC_OFF, DCOMP,
                            nullptr, nullptr, 0,
                            b_in_comp, nullptr, xc, NCOMP);

    // CSR scans + scatters
    int nbc = (NCOMP + 1023) / 1024;
    scan_block_k<<<nbc, 1024>>>(cnt_c, off_c, bsums, NCOMP);
    scan_sums_k<<<1, 128>>>(bsums, nbc);
    scan_add_k<<<nbc, 1024>>>(off_c, cur_c, bsums, NCOMP, NE);
    scatter_k<<<EB, 256>>>(ei_f2c_src, ei_f2c_dst, wf2c, cur_c, srcs_f2c, ws_f2c, NE);

    int nbf = (NFACT + 1023) / 1024;
    scan_block_k<<<nbf, 1024>>>(cnt_f, off_f, bsums, NFACT);
    scan_sums_k<<<1, 128>>>(bsums, nbf);
    scan_add_k<<<nbf, 1024>>>(off_f, cur_f, bsums, NFACT, NE);
    scatter_k<<<EB, 256>>>(ei_c2f_src, ei_c2f_dst, wc2f, cur_f, srcs_c2f, ws_c2f, NE);

    // message-passing layers
    float* cf = xf;  float* cc = xc;
    float* nf = xf2; float* nc = xc2;
    for (int l = 0; l < 2; l++) {
        aggregate_k<<<(NCOMP + 1) / 2, 256>>>(off_c, srcs_f2c, ws_f2c, cf, aggc, NCOMP);
        gemm_mma_k<<<GC, 256>>>(aggc, wt + WT_REL_OFF  + (l * 2 + 0) * 16384, 128,
                                cc,   wt + WT_ROOT_OFF + (l * 2 + 0) * 16384, 128,
                                b_rel + (l * 2 + 0) * 128, cc, nc, NCOMP);
        aggregate_k<<<(NFACT + 1) / 2, 256>>>(off_f, srcs_c2f, ws_c2f, cc, aggf, NFACT);
        gemm_mma_k<<<GF, 256>>>(aggf, wt + WT_REL_OFF  + (l * 2 + 1) * 16384, 128,
                                cf,   wt + WT_ROOT_OFF + (l * 2 + 1) * 16384, 128,
                                b_rel + (l * 2 + 1) * 128, cf, nf, NFACT);
        layernorm_k<<<NFACT, 128>>>(nf, ln_scale,       ln_bias,       NFACT);
        layernorm_k<<<NCOMP, 128>>>(nc, ln_scale + 128, ln_bias + 128, NCOMP);
        float* t;
        t = cf; cf = nf; nf = t;
        t = cc; cc = nc; nc = t;
    }

    // pooling + classifier
    pool_k<<<(NFACT * 128 + 255) / 256, 256>>>(cf, fact_batch, pool, pcnt, NFACT, 0, 0);
    pool_k<<<(NCOMP * 128 + 255) / 256, 256>>>(cc, comp_batch, pool, pcnt, NCOMP, 128, NBATCH);
    pmean_k<<<64, 256>>>(pool, pcnt, pmean);
    classifier_k<<<1, 128>>>(pmean, Wc1, bc1, Wc2, bc2, out);
}

// round 5
// speedup vs baseline: 1.3649x; 1.1169x over previous
#include <cuda_runtime.h>
#include <math.h>
#include <stdint.h>

#define H128 128
#define NFACT 100000
#define NCOMP 5000
#define NE 500000
#define NBATCH 64
#define DFACT 384
#define DCOMP 64

// ------------------------- static scratch (device .bss) -------------------------
__device__ float g_xf  [NFACT * H128];
__device__ float g_xf2 [NFACT * H128];
__device__ float g_aggf[NFACT * H128];
__device__ float g_xc  [NCOMP * H128];
__device__ float g_xc2 [NCOMP * H128];
__device__ float g_aggc[NCOMP * H128];
__device__ float g_wf2c[NE];
__device__ float g_wc2f[NE];
__device__ int   g_srcs_f2c[NE];
__device__ float g_ws_f2c  [NE];
__device__ int   g_srcs_c2f[NE];
__device__ float g_ws_c2f  [NE];
__device__ int   g_off_c[NCOMP + 1];
__device__ int   g_off_f[NFACT + 1];
__device__ int   g_cur_c[NCOMP];
__device__ int   g_cur_f[NFACT];
__device__ int   g_cnt_c[NCOMP];
__device__ int   g_cnt_f[NFACT];
__device__ int   g_bsums[256];
__device__ float g_pool [NBATCH * 256];
__device__ float g_pcnt [2 * NBATCH];
__device__ float g_pmean[NBATCH * 256];
// transposed weights: Wt_in_fact [128x384], Wt_in_comp [128x64], Wt_rel[4][128x128], Wt_root[4][128x128]
#define WT_INF_OFF  0
#define WT_INC_OFF  (128 * 384)
#define WT_REL_OFF  (WT_INC_OFF + 128 * 64)
#define WT_ROOT_OFF (WT_REL_OFF + 4 * 128 * 128)
__device__ float g_wt[WT_ROOT_OFF + 4 * 128 * 128];

// ------------------------- tf32 mma.sync GEMM (cp.async pipelined) -------------------------
__device__ __forceinline__ void mma16n8k8(float* c, const uint32_t* a, const uint32_t* b) {
    asm volatile(
        "mma.sync.aligned.m16n8k8.row.col.f32.tf32.tf32.f32 "
        "{%0,%1,%2,%3}, {%4,%5,%6,%7}, {%8,%9}, {%0,%1,%2,%3};"
        : "+f"(c[0]), "+f"(c[1]), "+f"(c[2]), "+f"(c[3])
        : "r"(a[0]), "r"(a[1]), "r"(a[2]), "r"(a[3]), "r"(b[0]), "r"(b[1]));
}
__device__ __forceinline__ uint32_t smem_u32(const void* p) {
    uint32_t a;
    asm("{ .reg .u64 t; cvta.to.shared.u64 t, %1; cvt.u32.u64 %0, t; }" : "=r"(a) : "l"(p));
    return a;
}
__device__ __forceinline__ void cp16(uint32_t dst, const void* src, int sz) {
    asm volatile("cp.async.ca.shared.global [%0], [%1], 16, %2;" :: "r"(dst), "l"(src), "r"(sz));
}
#define CP_COMMIT() asm volatile("cp.async.commit_group;" ::: "memory")
#define CP_WAIT1()  asm volatile("cp.async.wait_group 1;" ::: "memory")
#define CP_WAIT0()  asm volatile("cp.async.wait_group 0;" ::: "memory")

// per-stage layout (words): A tile 128x36, B tile 128x36
#define TPITCH 36
#define ATILE  (128 * TPITCH)
#define STAGEW (2 * ATILE)
#define GEMM_SMEM_BYTES (2 * STAGEW * 4)

// C[M,128] = relu( A1[M,K1] @ B1t^T + (A2[M,K2] @ B2t^T) + bias ) (+ prev)
__global__ void __launch_bounds__(256) gemm_mma_k(
    const float* __restrict__ A1, const float* __restrict__ B1t, int K1,
    const float* __restrict__ A2, const float* __restrict__ B2t, int K2,
    const float* __restrict__ bias, const float* __restrict__ prev,
    float* __restrict__ C, int M)
{
    extern __shared__ uint32_t sm[];
    const int tid  = threadIdx.x;
    const int lane = tid & 31;
    const int warp = tid >> 5;
    const int wm   = warp & 3;     // M quadrant
    const int wn   = warp >> 2;    // N half
    const int g    = lane >> 2;
    const int tg   = lane & 3;
    const int m0   = blockIdx.x * 128;
    const uint32_t sbase = smem_u32(sm);

    float acc[2][8][4];
    #pragma unroll
    for (int mf = 0; mf < 2; mf++)
        #pragma unroll
        for (int nf = 0; nf < 8; nf++)
            #pragma unroll
            for (int i = 0; i < 4; i++) acc[mf][nf][i] = 0.f;

    const int nch1 = K1 >> 5;
    const int nch2 = K2 >> 5;
    const int total = nch1 + nch2;

    // per-thread load coords: 4 x 16B for A, 4 x 16B for B
    const int lr  = tid >> 1;              // unused pattern base; use idx scheme below

    auto issue_loads = [&](int ch, int stage) {
        const float* A; const float* B; int K, k0;
        if (ch < nch1) { A = A1; B = B1t; K = K1; k0 = ch << 5; }
        else           { A = A2; B = B2t; K = K2; k0 = (ch - nch1) << 5; }
        uint32_t abase = sbase + stage * STAGEW * 4;
        uint32_t bbase = abase + ATILE * 4;
        #pragma unroll
        for (int i = 0; i < 4; i++) {
            int idx = i * 256 + tid;          // 0..1023
            int r = idx >> 3, c4 = idx & 7;   // row, 16B-chunk
            int sz = (m0 + r < M) ? 16 : 0;
            cp16(abase + (r * TPITCH + c4 * 4) * 4,
                 &A[(size_t)(m0 + r < M ? m0 + r : 0) * K + k0 + c4 * 4], sz);
        }
        #pragma unroll
        for (int i = 0; i < 4; i++) {
            int idx = i * 256 + tid;
            int r = idx >> 3, c4 = idx & 7;
            cp16(bbase + (r * TPITCH + c4 * 4) * 4,
                 &B[(size_t)r * K + k0 + c4 * 4], 16);
        }
        CP_COMMIT();
    };

    issue_loads(0, 0);

    for (int ch = 0; ch < total; ch++) {
        const int stage = ch & 1;
        if (ch + 1 < total) {
            issue_loads(ch + 1, stage ^ 1);
            CP_WAIT1();
        } else {
            CP_WAIT0();
        }
        __syncthreads();

        const uint32_t* As = sm + stage * STAGEW;
        const uint32_t* Bs = As + ATILE;

        #pragma unroll
        for (int s = 0; s < 4; s++) {
            const int kk = s * 8;
            uint32_t a[2][4], b[8][2];
            #pragma unroll
            for (int mf = 0; mf < 2; mf++) {
                int rb = wm * 32 + mf * 16;
                a[mf][0] = As[(rb + g    ) * TPITCH + kk + tg    ];
                a[mf][1] = As[(rb + 8 + g) * TPITCH + kk + tg    ];
                a[mf][2] = As[(rb + g    ) * TPITCH + kk + tg + 4];
                a[mf][3] = As[(rb + 8 + g) * TPITCH + kk + tg + 4];
            }
            #pragma unroll
            for (int nf = 0; nf < 8; nf++) {
                int cb = wn * 64 + nf * 8;
                b[nf][0] = Bs[(cb + g) * TPITCH + kk + tg    ];
                b[nf][1] = Bs[(cb + g) * TPITCH + kk + tg + 4];
            }
            #pragma unroll
            for (int mf = 0; mf < 2; mf++)
                #pragma unroll
                for (int nf = 0; nf < 8; nf++)
                    mma16n8k8(acc[mf][nf], a[mf], b[nf]);
        }
        __syncthreads();
    }

    // epilogue: bias + relu (+ prev residual)
    #pragma unroll
    for (int mf = 0; mf < 2; mf++) {
        #pragma unroll
        for (int nf = 0; nf < 8; nf++) {
            int col  = wn * 64 + nf * 8 + tg * 2;
            int row0 = m0 + wm * 32 + mf * 16 + g;
            float b0 = __ldg(&bias[col]);
            float b1 = __ldg(&bias[col + 1]);
            if (row0 < M) {
                float2 o;
                o.x = fmaxf(acc[mf][nf][0] + b0, 0.f);
                o.y = fmaxf(acc[mf][nf][1] + b1, 0.f);
                if (prev) {
                    float2 p = *(const float2*)&prev[(size_t)row0 * 128 + col];
                    o.x += p.x; o.y += p.y;
                }
                *(float2*)&C[(size_t)row0 * 128 + col] = o;
            }
            int row1 = row0 + 8;
            if (row1 < M) {
                float2 o;
                o.x = fmaxf(acc[mf][nf][2] + b0, 0.f);
                o.y = fmaxf(acc[mf][nf][3] + b1, 0.f);
                if (prev) {
                    float2 p = *(const float2*)&prev[(size_t)row1 * 128 + col];
                    o.x += p.x; o.y += p.y;
                }
                *(float2*)&C[(size_t)row1 * 128 + col] = o;
            }
        }
    }
}

// ------------------------- weight transpose -------------------------
__global__ void transpose_all_k(const float* __restrict__ W_in_fact,
                                const float* __restrict__ W_in_comp,
                                const float* __restrict__ W_rel,
                                const float* __restrict__ W_root,
                                float* __restrict__ wt)
{
    int i = blockIdx.x * 256 + threadIdx.x;
    int total0 = 384 * 128;
    int total1 = 64 * 128;
    int total2 = 4 * 128 * 128;
    if (i < total0) {
        int k = i >> 7, n = i & 127;
        wt[WT_INF_OFF + n * 384 + k] = W_in_fact[i];
    }
    if (i < total1) {
        int k = i >> 7, n = i & 127;
        wt[WT_INC_OFF + n * 64 + k] = W_in_comp[i];
    }
    if (i < total2) {
        int m = i / 16384, r = i % 16384;
        int k = r >> 7, n = r & 127;
        wt[WT_REL_OFF  + m * 16384 + n * 128 + k] = W_rel[i];
        wt[WT_ROOT_OFF + m * 16384 + n * 128 + k] = W_root[i];
    }
}

// ------------------------- edge gate MLP (fast trig via identities) -------------------------
__global__ void edge_gate_k(const float* __restrict__ ea,
                            const float* __restrict__ eW1, const float* __restrict__ eb1,
                            const float* __restrict__ eW2, const float* __restrict__ eb2,
                            const float* __restrict__ eW3, const float* __restrict__ eb3,
                            float* __restrict__ w)
{
    __shared__ float sW1[11 * 32], sb1[32], sW2[32 * 16], sb2[16], sW3[16], sb3;
    int tid = threadIdx.x;
    for (int i = tid; i < 11 * 32; i += blockDim.x) sW1[i] = eW1[i];
    for (int i = tid; i < 32 * 16; i += blockDim.x) sW2[i] = eW2[i];
    if (tid < 32) sb1[tid] = eb1[tid];
    if (tid < 16) { sb2[tid] = eb2[tid]; sW3[tid] = eW3[tid]; }
    if (tid == 0) sb3 = eb3[0];
    __syncthreads();

    int e = blockIdx.x * blockDim.x + tid;
    if (e >= NE) return;

    float sent  = fminf(fmaxf(ea[2 * e + 0], -1.f), 1.f);
    float decay = ea[2 * e + 1];
    float dt = fmaxf(-logf(fmaxf(decay, 1e-6f)) * 100.0f, 0.f);   // LAM = 0.01
    float ds = fminf(fmaxf(dt * (1.f / 30.f), 0.f), 12.f);

    float s1, c1;
    sincosf(ds, &s1, &c1);
    // exact multiple-angle identities
    float s2 = 2.f * s1 * c1;
    float c2 = 1.f - 2.f * s1 * s1;
    float s3 = s1 * c2 + c1 * s2;
    float c3 = c1 * c2 - s1 * s2;
    float s4 = 2.f * s2 * c2;
    float c4 = 1.f - 2.f * s2 * s2;

    float x[11];
    x[0] = sent;
    x[1] = log1pf(dt);
    x[2] = s1;  x[3] = s2;  x[4] = s3;  x[5] = s4;
    x[6] = c1;  x[7] = c2;  x[8] = c3;  x[9] = c4;
    x[10] = ds;

    float h1[32];
    #pragma unroll
    for (int j = 0; j < 32; j++) {
        float a = sb1[j];
        #pragma unroll
        for (int i = 0; i < 11; i++) a += x[i] * sW1[i * 32 + j];
        h1[j] = fmaxf(a, 0.f);
    }
    float h2[16];
    #pragma unroll
    for (int j = 0; j < 16; j++) {
        float a = sb2[j];
        #pragma unroll
        for (int i = 0; i < 32; i++) a += h1[i] * sW2[i * 16 + j];
        h2[j] = fmaxf(a, 0.f);
    }
    float z = sb3;
    #pragma unroll
    for (int i = 0; i < 16; i++) z += h2[i] * sW3[i];
    w[e] = 1.f / (1.f + __expf(-z));
}

// ------------------------- CSR build -------------------------
__global__ void hist_k(const int* __restrict__ dst, int* __restrict__ cnt, int n)
{
    int e = blockIdx.x * blockDim.x + threadIdx.x;
    if (e < n) atomicAdd(&cnt[dst[e]], 1);
}

__global__ void scan_block_k(const int* __restrict__ in, int* __restrict__ out,
                             int* __restrict__ bsums, int n)
{
    __shared__ int s[1024];
    int tid = threadIdx.x;
    int i = blockIdx.x * 1024 + tid;
    int v = (i < n) ? in[i] : 0;
    s[tid] = v;
    __syncthreads();
    for (int o = 1; o < 1024; o <<= 1) {
        int t = 0;
        if (tid >= o) t = s[tid - o];
        __syncthreads();
        if (tid >= o) s[tid] += t;
        __syncthreads();
    }
    if (i < n) out[i] = s[tid] - v;
    if (tid == 1023) bsums[blockIdx.x] = s[1023];
}

__global__ void scan_sums_k(int* __restrict__ bsums, int nb)
{
    __shared__ int s[128];
    int tid = threadIdx.x;
    int v = (tid < nb) ? bsums[tid] : 0;
    s[tid] = v;
    __syncthreads();
    for (int o = 1; o < 128; o <<= 1) {
        int t = 0;
        if (tid >= o) t = s[tid - o];
        __syncthreads();
        if (tid >= o) s[tid] += t;
        __syncthreads();
    }
    if (tid < nb) bsums[tid] = s[tid] - v;
}

__global__ void scan_add_k(int* __restrict__ off, int* __restrict__ cur,
                           const int* __restrict__ bsums, int n, int total)
{
    int i = blockIdx.x * 1024 + threadIdx.x;
    if (i < n) {
        int v = off[i] + bsums[blockIdx.x];
        off[i] = v;
        cur[i] = v;
    }
    if (i == 0) off[n] = total;
}

__global__ void scatter_k(const int* __restrict__ src, const int* __restrict__ dst,
                          const float* __restrict__ w, int* __restrict__ cur,
                          int* __restrict__ srcs_s, float* __restrict__ ws_s, int n)
{
    int e = blockIdx.x * blockDim.x + threadIdx.x;
    if (e >= n) return;
    int d = dst[e];
    int p = atomicAdd(&cur[d], 1);
    srcs_s[p] = src[e];
    ws_s[p]   = w[e];
}

// ------------------------- gather-side aggregation (no atomics) -------------------------
__global__ void aggregate_k(const int* __restrict__ off, const int* __restrict__ srcs,
                            const float* __restrict__ ws, const float* __restrict__ x,
                            float* __restrict__ out, int n)
{
    int node = blockIdx.x * 2 + (threadIdx.x >> 7);
    int c = threadIdx.x & 127;
    if (node >= n) return;
    int s = off[node], e = off[node + 1];
    float acc = 0.f;
    int i = s;
    for (; i + 4 <= e; i += 4) {
        int s0 = __ldg(&srcs[i]);     int s1 = __ldg(&srcs[i + 1]);
        int s2 = __ldg(&srcs[i + 2]); int s3 = __ldg(&srcs[i + 3]);
        float w0 = __ldg(&ws[i]);     float w1 = __ldg(&ws[i + 1]);
        float w2 = __ldg(&ws[i + 2]); float w3 = __ldg(&ws[i + 3]);
        float x0 = __ldg(&x[(size_t)s0 * 128 + c]);
        float x1 = __ldg(&x[(size_t)s1 * 128 + c]);
        float x2 = __ldg(&x[(size_t)s2 * 128 + c]);
        float x3 = __ldg(&x[(size_t)s3 * 128 + c]);
        acc += x0 * w0 + x1 * w1 + x2 * w2 + x3 * w3;
    }
    for (; i < e; i++)
        acc += __ldg(&x[(size_t)__ldg(&srcs[i]) * 128 + c]) * __ldg(&ws[i]);
    out[(size_t)node * 128 + c] = acc;
}

// ------------------------- layernorm -------------------------
__global__ void layernorm_k(float* __restrict__ x, const float* __restrict__ scale,
                            const float* __restrict__ bias, int n)
{
    int row = blockIdx.x;
    if (row >= n) return;
    int c = threadIdx.x;
    float v = x[(size_t)row * 128 + c];
    float s = v, s2 = v * v;
    #pragma unroll
    for (int o = 16; o > 0; o >>= 1) {
        s  += __shfl_xor_sync(0xffffffffu, s, o);
        s2 += __shfl_xor_sync(0xffffffffu, s2, o);
    }
    __shared__ float rs[4], rs2[4];
    if ((c & 31) == 0) { rs[c >> 5] = s; rs2[c >> 5] = s2; }
    __syncthreads();
    s  = rs[0] + rs[1] + rs[2] + rs[3];
    s2 = rs2[0] + rs2[1] + rs2[2] + rs2[3];
    float mu  = s * (1.f / 128.f);
    float var = s2 * (1.f / 128.f) - mu * mu;
    x[(size_t)row * 128 + c] = (v - mu) * rsqrtf(var + 1e-5f) * scale[c] + bias[c];
}

// ------------------------- pooling (sorted-run segment reduction) -------------------------
#define PROWS 64
__global__ void pool_seg_k(const float* __restrict__ x, const int* __restrict__ batch,
                           float* __restrict__ pool, float* __restrict__ pcnt,
                           int n, int coloff, int cntoff)
{
    int c = threadIdx.x;  // 128 threads, one per column
    int r0 = blockIdx.x * PROWS;
    int r1 = r0 + PROWS < n ? r0 + PROWS : n;
    if (r0 >= n) return;
    int curb = __ldg(&batch[r0]);
    float acc = 0.f, cnt = 0.f;
    for (int r = r0; r < r1; r++) {
        int b = __ldg(&batch[r]);
        if (b != curb) {
            atomicAdd(&pool[curb * 256 + coloff + c], acc);
            if (c == 0) atomicAdd(&pcnt[cntoff + curb], cnt);
            acc = 0.f; cnt = 0.f; curb = b;
        }
        acc += x[(size_t)r * 128 + c];
        cnt += 1.f;
    }
    atomicAdd(&pool[curb * 256 + coloff + c], acc);
    if (c == 0) atomicAdd(&pcnt[cntoff + curb], cnt);
}

__global__ void pmean_k(const float* __restrict__ pool, const float* __restrict__ pcnt,
                        float* __restrict__ pmean)
{
    int i = blockIdx.x * blockDim.x + threadIdx.x;
    if (i >= NBATCH * 256) return;
    int b = i >> 8, k = i & 255;
    float cnt = pcnt[(k < 128 ? 0 : NBATCH) + b];
    pmean[i] = pool[i] / fmaxf(cnt, 1.f);
}

__global__ void classifier_k(const float* __restrict__ pmean,
                             const float* __restrict__ Wc1, const float* __restrict__ bc1,
                             const float* __restrict__ Wc2, const float* __restrict__ bc2,
                             float* __restrict__ out)
{
    __shared__ float h[64][129];
    int c = threadIdx.x;  // 128 threads
    for (int b = 0; b < 64; b++) {
        float a = bc1[c];
        #pragma unroll 4
        for (int k = 0; k < 256; k++) a += pmean[b * 256 + k] * Wc1[k * 128 + c];
        h[b][c] = fmaxf(a, 0.f);
    }
    __syncthreads();
    if (c < 64) {
        float a = bc2[0];
        #pragma unroll 4
        for (int k = 0; k < 128; k++) a += h[c][k] * Wc2[k];
        out[c] = a;
    }
}

// ------------------------- host orchestration -------------------------
extern "C" void kernel_launch(void* const* d_in, const int* in_sizes, int n_in,
                              void* d_out, int out_size)
{
    const float* x_fact     = (const float*)d_in[0];
    const float* x_comp     = (const float*)d_in[1];
    const float* ea_f2c     = (const float*)d_in[2];
    const float* ea_c2f     = (const float*)d_in[3];
    const int*   ei_f2c_src = (const int*)d_in[4];
    const int*   ei_f2c_dst = (const int*)d_in[5];
    const int*   ei_c2f_src = (const int*)d_in[6];
    const int*   ei_c2f_dst = (const int*)d_in[7];
    const int*   fact_batch = (const int*)d_in[8];
    const int*   comp_batch = (const int*)d_in[9];
    const float* W_in_fact  = (const float*)d_in[10];
    const float* b_in_fact  = (const float*)d_in[11];
    const float* W_in_comp  = (const float*)d_in[12];
    const float* b_in_comp  = (const float*)d_in[13];
    const float* eW1 = (const float*)d_in[14];
    const float* eb1 = (const float*)d_in[15];
    const float* eW2 = (const float*)d_in[16];
    const float* eb2 = (const float*)d_in[17];
    const float* eW3 = (const float*)d_in[18];
    const float* eb3 = (const float*)d_in[19];
    const float* W_rel    = (const float*)d_in[20];
    const float* b_rel    = (const float*)d_in[21];
    const float* W_root   = (const float*)d_in[22];
    const float* ln_scale = (const float*)d_in[23];
    const float* ln_bias  = (const float*)d_in[24];
    const float* Wc1 = (const float*)d_in[25];
    const float* bc1 = (const float*)d_in[26];
    const float* Wc2 = (const float*)d_in[27];
    const float* bc2 = (const float*)d_in[28];
    float* out = (float*)d_out;

    float *xf, *xf2, *aggf, *xc, *xc2, *aggc, *wf2c, *wc2f;
    float *ws_f2c, *ws_c2f, *pool, *pcnt, *pmean, *wt;
    int *srcs_f2c, *srcs_c2f, *off_c, *off_f, *cur_c, *cur_f, *cnt_c, *cnt_f, *bsums;
    cudaGetSymbolAddress((void**)&xf,   g_xf);
    cudaGetSymbolAddress((void**)&xf2,  g_xf2);
    cudaGetSymbolAddress((void**)&aggf, g_aggf);
    cudaGetSymbolAddress((void**)&xc,   g_xc);
    cudaGetSymbolAddress((void**)&xc2,  g_xc2);
    cudaGetSymbolAddress((void**)&aggc, g_aggc);
    cudaGetSymbolAddress((void**)&wf2c, g_wf2c);
    cudaGetSymbolAddress((void**)&wc2f, g_wc2f);
    cudaGetSymbolAddress((void**)&srcs_f2c, g_srcs_f2c);
    cudaGetSymbolAddress((void**)&ws_f2c,   g_ws_f2c);
    cudaGetSymbolAddress((void**)&srcs_c2f, g_srcs_c2f);
    cudaGetSymbolAddress((void**)&ws_c2f,   g_ws_c2f);
    cudaGetSymbolAddress((void**)&off_c, g_off_c);
    cudaGetSymbolAddress((void**)&off_f, g_off_f);
    cudaGetSymbolAddress((void**)&cur_c, g_cur_c);
    cudaGetSymbolAddress((void**)&cur_f, g_cur_f);
    cudaGetSymbolAddress((void**)&cnt_c, g_cnt_c);
    cudaGetSymbolAddress((void**)&cnt_f, g_cnt_f);
    cudaGetSymbolAddress((void**)&bsums, g_bsums);
    cudaGetSymbolAddress((void**)&pool,  g_pool);
    cudaGetSymbolAddress((void**)&pcnt,  g_pcnt);
    cudaGetSymbolAddress((void**)&pmean, g_pmean);
    cudaGetSymbolAddress((void**)&wt,    g_wt);

    static int smem_set = 0;
    if (!smem_set) {
        cudaFuncSetAttribute(gemm_mma_k, cudaFuncAttributeMaxDynamicSharedMemorySize,
                             GEMM_SMEM_BYTES);
        smem_set = 1;
    }

    cudaMemsetAsync(cnt_c, 0, NCOMP * sizeof(int));
    cudaMemsetAsync(cnt_f, 0, NFACT * sizeof(int));
    cudaMemsetAsync(pool,  0, NBATCH * 256 * sizeof(float));
    cudaMemsetAsync(pcnt,  0, 2 * NBATCH * sizeof(float));

    const int EB = (NE + 255) / 256;
    const int GF = (NFACT + 127) / 128;
    const int GC = (NCOMP + 127) / 128;

    transpose_all_k<<<256, 256>>>(W_in_fact, W_in_comp, W_rel, W_root, wt);

    edge_gate_k<<<EB, 256>>>(ea_f2c, eW1, eb1, eW2, eb2, eW3, eb3, wf2c);
    edge_gate_k<<<EB, 256>>>(ea_c2f, eW1, eb1, eW2, eb2, eW3, eb3, wc2f);
    hist_k<<<EB, 256>>>(ei_f2c_dst, cnt_c, NE);
    hist_k<<<EB, 256>>>(ei_c2f_dst, cnt_f, NE);

    gemm_mma_k<<<GF, 256, GEMM_SMEM_BYTES>>>(x_fact, wt + WT_INF_OFF, DFACT,
                                             nullptr, nullptr, 0,
                                             b_in_fact, nullptr, xf, NFACT);
    gemm_mma_k<<<GC, 256, GEMM_SMEM_BYTES>>>(x_comp, wt + WT_INC_OFF, DCOMP,
                                             nullptr, nullptr, 0,
                                             b_in_comp, nullptr, xc, NCOMP);

    int nbc = (NCOMP + 1023) / 1024;
    scan_block_k<<<nbc, 1024>>>(cnt_c, off_c, bsums, NCOMP);
    scan_sums_k<<<1, 128>>>(bsums, nbc);
    scan_add_k<<<nbc, 1024>>>(off_c, cur_c, bsums, NCOMP, NE);
    scatter_k<<<EB, 256>>>(ei_f2c_src, ei_f2c_dst, wf2c, cur_c, srcs_f2c, ws_f2c, NE);

    int nbf = (NFACT + 1023) / 1024;
    scan_block_k<<<nbf, 1024>>>(cnt_f, off_f, bsums, NFACT);
    scan_sums_k<<<1, 128>>>(bsums, nbf);
    scan_add_k<<<nbf, 1024>>>(off_f, cur_f, bsums, NFACT, NE);
    scatter_k<<<EB, 256>>>(ei_c2f_src, ei_c2f_dst, wc2f, cur_f, srcs_c2f, ws_c2f, NE);

    float* cf = xf;  float* cc = xc;
    float* nf = xf2; float* nc = xc2;
    for (int l = 0; l < 2; l++) {
        aggregate_k<<<(NCOMP + 1) / 2, 256>>>(off_c, srcs_f2c, ws_f2c, cf, aggc, NCOMP);
        gemm_mma_k<<<GC, 256, GEMM_SMEM_BYTES>>>(aggc, wt + WT_REL_OFF  + (l * 2 + 0) * 16384, 128,
                                                 cc,   wt + WT_ROOT_OFF + (l * 2 + 0) * 16384, 128,
                                                 b_rel + (l * 2 + 0) * 128, cc, nc, NCOMP);
        aggregate_k<<<(NFACT + 1) / 2, 256>>>(off_f, srcs_c2f, ws_c2f, cc, aggf, NFACT);
        gemm_mma_k<<<GF, 256, GEMM_SMEM_BYTES>>>(aggf, wt + WT_REL_OFF  + (l * 2 + 1) * 16384, 128,
                                                 cf,   wt + WT_ROOT_OFF + (l * 2 + 1) * 16384, 128,
                                                 b_rel + (l * 2 + 1) * 128, cf, nf, NFACT);
        layernorm_k<<<NFACT, 128>>>(nf, ln_scale,       ln_bias,       NFACT);
        layernorm_k<<<NCOMP, 128>>>(nc, ln_scale + 128, ln_bias + 128, NCOMP);
        float* t;
        t = cf; cf = nf; nf = t;
        t = cc; cc = nc; nc = t;
    }

    pool_seg_k<<<(NFACT + PROWS - 1) / PROWS, 128>>>(cf, fact_batch, pool, pcnt, NFACT, 0, 0);
    pool_seg_k<<<(NCOMP + PROWS - 1) / PROWS, 128>>>(cc, comp_batch, pool, pcnt, NCOMP, 128, NBATCH);
    pmean_k<<<64, 256>>>(pool, pcnt, pmean);
    classifier_k<<<1, 128>>>(pmean, Wc1, bc1, Wc2, bc2, out);
}